// round 1
// baseline (speedup 1.0000x reference)
#include <cuda_runtime.h>
#include <cuda_bf16.h>
#include <cstdint>

#define BSZ   2
#define QLEN  2048
#define DIM   2048
#define NH    16
#define DHD   128
#define MTOK  (BSZ * QLEN)   // 4096

// ---------------- scratch (static device memory; no allocation) -------------
__device__ float g_q[(size_t)MTOK * DIM];
__device__ float g_k[(size_t)MTOK * DIM];
__device__ float g_v[(size_t)MTOK * DIM];
__device__ float g_ctx[(size_t)MTOK * DIM];

// ---------------- GEMM: C[m][n] = sum_k A[m][k]*W[n][k] + bias[n] -----------
// A: [M,K] row-major, W: [N,K] row-major (torch Linear weight), C: [M,N]
__global__ __launch_bounds__(256) void gemm_nt_bias(
    const float* __restrict__ A, const float* __restrict__ W,
    const float* __restrict__ bias, float* __restrict__ C,
    int M, int N, int K)
{
    __shared__ float As[16][132];
    __shared__ float Ws[16][132];

    const int tid = threadIdx.x;
    const int m0 = blockIdx.y * 128;
    const int n0 = blockIdx.x * 128;
    const int tx = tid & 15;        // 0..15  (cols)
    const int ty = tid >> 4;        // 0..15  (rows)
    const int ir = tid >> 2;        // 0..63  (load row)
    const int ic = tid & 3;         // 0..3   (load col-group of 4)

    float acc[8][8];
#pragma unroll
    for (int i = 0; i < 8; ++i)
#pragma unroll
        for (int j = 0; j < 8; ++j) acc[i][j] = 0.f;

    const float* Aptr = A + (size_t)(m0 + ir) * K + ic * 4;
    const float* Wptr = W + (size_t)(n0 + ir) * K + ic * 4;
    const size_t rowskip = (size_t)64 * K;

    for (int k0 = 0; k0 < K; k0 += 16) {
        float4 a0 = *(const float4*)(Aptr + k0);
        float4 a1 = *(const float4*)(Aptr + rowskip + k0);
        float4 w0 = *(const float4*)(Wptr + k0);
        float4 w1 = *(const float4*)(Wptr + rowskip + k0);

        As[ic * 4 + 0][ir]      = a0.x;
        As[ic * 4 + 1][ir]      = a0.y;
        As[ic * 4 + 2][ir]      = a0.z;
        As[ic * 4 + 3][ir]      = a0.w;
        As[ic * 4 + 0][ir + 64] = a1.x;
        As[ic * 4 + 1][ir + 64] = a1.y;
        As[ic * 4 + 2][ir + 64] = a1.z;
        As[ic * 4 + 3][ir + 64] = a1.w;

        Ws[ic * 4 + 0][ir]      = w0.x;
        Ws[ic * 4 + 1][ir]      = w0.y;
        Ws[ic * 4 + 2][ir]      = w0.z;
        Ws[ic * 4 + 3][ir]      = w0.w;
        Ws[ic * 4 + 0][ir + 64] = w1.x;
        Ws[ic * 4 + 1][ir + 64] = w1.y;
        Ws[ic * 4 + 2][ir + 64] = w1.z;
        Ws[ic * 4 + 3][ir + 64] = w1.w;

        __syncthreads();

#pragma unroll
        for (int kk = 0; kk < 16; ++kk) {
            float4 ra0 = *(const float4*)&As[kk][ty * 8];
            float4 ra1 = *(const float4*)&As[kk][ty * 8 + 4];
            float4 rb0 = *(const float4*)&Ws[kk][tx * 8];
            float4 rb1 = *(const float4*)&Ws[kk][tx * 8 + 4];
            float ra[8] = {ra0.x, ra0.y, ra0.z, ra0.w, ra1.x, ra1.y, ra1.z, ra1.w};
            float rb[8] = {rb0.x, rb0.y, rb0.z, rb0.w, rb1.x, rb1.y, rb1.z, rb1.w};
#pragma unroll
            for (int i = 0; i < 8; ++i)
#pragma unroll
                for (int j = 0; j < 8; ++j)
                    acc[i][j] = fmaf(ra[i], rb[j], acc[i][j]);
        }
        __syncthreads();
    }

    float bj[8];
#pragma unroll
    for (int j = 0; j < 8; ++j) bj[j] = bias[n0 + tx * 8 + j];

#pragma unroll
    for (int i = 0; i < 8; ++i) {
        float* cp = C + (size_t)(m0 + ty * 8 + i) * N + n0 + tx * 8;
#pragma unroll
        for (int j = 0; j < 8; ++j) cp[j] = acc[i][j] + bj[j];
    }
}

// ---------------- Flash-style attention -------------------------------------
// Q/K/V stored as [b, q, h*DHD] row-major; per (b,h,q-tile) CTA.
#define BQ 64
#define BKT 64
#define QPITCH 132     // 128 + 4 (float4-aligned pad)
#define KPITCH 68      // 64 + 4   (transposed K: [d][j])
#define SPITCH 65

#define ATTN_SMEM_FLOATS (BQ*QPITCH + DHD*KPITCH + BKT*QPITCH + BQ*SPITCH + 3*BQ + BKT)
#define ATTN_SMEM_BYTES  (ATTN_SMEM_FLOATS * 4)

__global__ __launch_bounds__(256) void attn_kernel(
    const float* __restrict__ Qm, const float* __restrict__ Km,
    const float* __restrict__ Vm, const int* __restrict__ mask,
    float* __restrict__ ctx)
{
    extern __shared__ float sm[];
    float* Qs   = sm;                       // [BQ][QPITCH]
    float* Kts  = Qs  + BQ  * QPITCH;       // [DHD][KPITCH] (transposed)
    float* Vs   = Kts + DHD * KPITCH;       // [BKT][QPITCH]
    float* Sb   = Vs  + BKT * QPITCH;       // [BQ][SPITCH]
    float* rowm = Sb  + BQ  * SPITCH;
    float* rowl = rowm + BQ;
    float* rowscale = rowl + BQ;
    int*   mk   = (int*)(rowscale + BQ);

    const int b  = blockIdx.z;
    const int h  = blockIdx.y;
    const int q0 = blockIdx.x * BQ;
    const int tid = threadIdx.x;
    const int ti = tid >> 4;   // 0..15 -> rows 4*ti..4*ti+3
    const int tj = tid & 15;   // 0..15 -> S cols 4*tj..  / O cols 8*tj..
    const float scale = 0.08838834764831845f;  // 1/sqrt(128)

    // load Q tile (64 x 128)
    const float* Qbase = Qm + (size_t)(b * QLEN + q0) * DIM + h * DHD;
#pragma unroll
    for (int it = 0; it < 8; ++it) {
        int idx = tid + it * 256;           // 0..2047 -> 64 rows x 32 float4
        int r = idx >> 5, c4 = idx & 31;
        float4 v = *(const float4*)(Qbase + (size_t)r * DIM + c4 * 4);
        *(float4*)&Qs[r * QPITCH + c4 * 4] = v;
    }
    if (tid < BQ) { rowm[tid] = -1e30f; rowl[tid] = 0.f; }

    float acc[4][8];
#pragma unroll
    for (int i = 0; i < 4; ++i)
#pragma unroll
        for (int c = 0; c < 8; ++c) acc[i][c] = 0.f;

    __syncthreads();

    for (int k0 = 0; k0 < QLEN; k0 += BKT) {
        const float* Kbase = Km + (size_t)(b * QLEN + k0) * DIM + h * DHD;
        const float* Vbase = Vm + (size_t)(b * QLEN + k0) * DIM + h * DHD;
#pragma unroll
        for (int it = 0; it < 8; ++it) {
            int idx = tid + it * 256;
            int r = idx >> 5, c4 = idx & 31;
            float4 kv = *(const float4*)(Kbase + (size_t)r * DIM + c4 * 4);
            Kts[(c4 * 4 + 0) * KPITCH + r] = kv.x;
            Kts[(c4 * 4 + 1) * KPITCH + r] = kv.y;
            Kts[(c4 * 4 + 2) * KPITCH + r] = kv.z;
            Kts[(c4 * 4 + 3) * KPITCH + r] = kv.w;
            float4 vv = *(const float4*)(Vbase + (size_t)r * DIM + c4 * 4);
            *(float4*)&Vs[r * QPITCH + c4 * 4] = vv;
        }
        if (tid < BKT) mk[tid] = mask[b * QLEN + k0 + tid];
        __syncthreads();

        // S = Q K^T  (each thread: rows 4*ti.., cols 4*tj..)
        float s[4][4];
#pragma unroll
        for (int i = 0; i < 4; ++i)
#pragma unroll
            for (int j = 0; j < 4; ++j) s[i][j] = 0.f;

#pragma unroll 8
        for (int d = 0; d < DHD; ++d) {
            float4 kv = *(const float4*)&Kts[d * KPITCH + tj * 4];
            float qv0 = Qs[(ti * 4 + 0) * QPITCH + d];
            float qv1 = Qs[(ti * 4 + 1) * QPITCH + d];
            float qv2 = Qs[(ti * 4 + 2) * QPITCH + d];
            float qv3 = Qs[(ti * 4 + 3) * QPITCH + d];
            s[0][0] = fmaf(qv0, kv.x, s[0][0]); s[0][1] = fmaf(qv0, kv.y, s[0][1]);
            s[0][2] = fmaf(qv0, kv.z, s[0][2]); s[0][3] = fmaf(qv0, kv.w, s[0][3]);
            s[1][0] = fmaf(qv1, kv.x, s[1][0]); s[1][1] = fmaf(qv1, kv.y, s[1][1]);
            s[1][2] = fmaf(qv1, kv.z, s[1][2]); s[1][3] = fmaf(qv1, kv.w, s[1][3]);
            s[2][0] = fmaf(qv2, kv.x, s[2][0]); s[2][1] = fmaf(qv2, kv.y, s[2][1]);
            s[2][2] = fmaf(qv2, kv.z, s[2][2]); s[2][3] = fmaf(qv2, kv.w, s[2][3]);
            s[3][0] = fmaf(qv3, kv.x, s[3][0]); s[3][1] = fmaf(qv3, kv.y, s[3][1]);
            s[3][2] = fmaf(qv3, kv.z, s[3][2]); s[3][3] = fmaf(qv3, kv.w, s[3][3]);
        }

#pragma unroll
        for (int jj = 0; jj < 4; ++jj) {
            int j = tj * 4 + jj;
            bool live = (mk[j] != 0);
#pragma unroll
            for (int ii = 0; ii < 4; ++ii) {
                float v = live ? s[ii][jj] * scale : -1e30f;
                Sb[(ti * 4 + ii) * SPITCH + j] = v;
            }
        }
        __syncthreads();

        // online softmax per row (one thread per row)
        if (tid < BQ) {
            float mold = rowm[tid];
            float mx = mold;
            float* srow = &Sb[tid * SPITCH];
#pragma unroll 8
            for (int j = 0; j < BKT; ++j) mx = fmaxf(mx, srow[j]);
            float corr = __expf(mold - mx);
            float l = rowl[tid] * corr;
#pragma unroll 8
            for (int j = 0; j < BKT; ++j) {
                float p = __expf(srow[j] - mx);
                srow[j] = p;
                l += p;
            }
            rowm[tid] = mx; rowl[tid] = l; rowscale[tid] = corr;
        }
        __syncthreads();

        // rescale accumulators, then O += P V  (rows 4*ti.., cols 8*tj..)
#pragma unroll
        for (int ii = 0; ii < 4; ++ii) {
            float cs = rowscale[ti * 4 + ii];
#pragma unroll
            for (int c = 0; c < 8; ++c) acc[ii][c] *= cs;
        }
#pragma unroll 4
        for (int j = 0; j < BKT; ++j) {
            float4 v0 = *(const float4*)&Vs[j * QPITCH + tj * 8];
            float4 v1 = *(const float4*)&Vs[j * QPITCH + tj * 8 + 4];
#pragma unroll
            for (int ii = 0; ii < 4; ++ii) {
                float p = Sb[(ti * 4 + ii) * SPITCH + j];
                acc[ii][0] = fmaf(p, v0.x, acc[ii][0]);
                acc[ii][1] = fmaf(p, v0.y, acc[ii][1]);
                acc[ii][2] = fmaf(p, v0.z, acc[ii][2]);
                acc[ii][3] = fmaf(p, v0.w, acc[ii][3]);
                acc[ii][4] = fmaf(p, v1.x, acc[ii][4]);
                acc[ii][5] = fmaf(p, v1.y, acc[ii][5]);
                acc[ii][6] = fmaf(p, v1.z, acc[ii][6]);
                acc[ii][7] = fmaf(p, v1.w, acc[ii][7]);
            }
        }
        __syncthreads();
    }

    // epilogue: divide by l, write ctx[b][q][h*DHD + c]
#pragma unroll
    for (int ii = 0; ii < 4; ++ii) {
        int row = ti * 4 + ii;
        float inv = 1.0f / rowl[row];
        float* op = ctx + (size_t)(b * QLEN + q0 + row) * DIM + h * DHD + tj * 8;
#pragma unroll
        for (int c = 0; c < 8; ++c) op[c] = acc[ii][c] * inv;
    }
}

// ---------------- launch -----------------------------------------------------
extern "C" void kernel_launch(void* const* d_in, const int* in_sizes, int n_in,
                              void* d_out, int out_size)
{
    const float* x    = (const float*)d_in[0];
    const int*   mask = (const int*)d_in[1];
    const float* wq   = (const float*)d_in[2];
    const float* bq   = (const float*)d_in[3];
    const float* wk   = (const float*)d_in[4];
    const float* bk   = (const float*)d_in[5];
    const float* wv   = (const float*)d_in[6];
    const float* bv   = (const float*)d_in[7];
    const float* wo   = (const float*)d_in[8];
    const float* bo   = (const float*)d_in[9];
    float* out = (float*)d_out;

    float *gq, *gk, *gv, *gctx;
    cudaGetSymbolAddress((void**)&gq,  g_q);
    cudaGetSymbolAddress((void**)&gk,  g_k);
    cudaGetSymbolAddress((void**)&gv,  g_v);
    cudaGetSymbolAddress((void**)&gctx, g_ctx);

    dim3 gemm_grid(DIM / 128, MTOK / 128);   // (16, 32)
    gemm_nt_bias<<<gemm_grid, 256>>>(x, wq, bq, gq, MTOK, DIM, DIM);
    gemm_nt_bias<<<gemm_grid, 256>>>(x, wk, bk, gk, MTOK, DIM, DIM);
    gemm_nt_bias<<<gemm_grid, 256>>>(x, wv, bv, gv, MTOK, DIM, DIM);

    cudaFuncSetAttribute(attn_kernel, cudaFuncAttributeMaxDynamicSharedMemorySize,
                         ATTN_SMEM_BYTES);
    attn_kernel<<<dim3(QLEN / BQ, NH, BSZ), 256, ATTN_SMEM_BYTES>>>(
        gq, gk, gv, mask, gctx);

    gemm_nt_bias<<<gemm_grid, 256>>>(gctx, wo, bo, out, MTOK, DIM, DIM);
}

// round 3
// speedup vs baseline: 1.5856x; 1.5856x over previous
#include <cuda_runtime.h>
#include <cuda_bf16.h>
#include <cstdint>

#define BSZ   2
#define QLEN  2048
#define DIM   2048
#define NH    16
#define DHD   128
#define MTOK  (BSZ * QLEN)   // 4096

// ---------------- scratch (static device memory; no allocation) -------------
__device__ float g_q[(size_t)MTOK * DIM];
__device__ float g_k[(size_t)MTOK * DIM];
__device__ float g_v[(size_t)MTOK * DIM];
__device__ float g_ctx[(size_t)MTOK * DIM];
__device__ float g_xr[(size_t)MTOK * DIM];          // tf32-rounded input
__device__ float g_wr[4][(size_t)DIM * DIM];        // tf32-rounded weights

// ======================= helpers =============================================
__device__ __forceinline__ float tf32r(float x) {
    uint32_t r;
    asm("cvt.rna.tf32.f32 %0, %1;" : "=r"(r) : "f"(x));
    return __uint_as_float(r);
}

#define CP_ASYNC16(dst, src) \
    asm volatile("cp.async.cg.shared.global [%0], [%1], 16;" :: "r"(dst), "l"(src))
#define CP_COMMIT() asm volatile("cp.async.commit_group;" ::: "memory")
#define CP_WAIT(n)  asm volatile("cp.async.wait_group %0;" :: "n"(n) : "memory")

__device__ __forceinline__ uint32_t smem_u32(const void* p) {
    uint32_t a;
    asm("{ .reg .u64 t; cvta.to.shared.u64 t, %1; cvt.u32.u64 %0, t; }"
        : "=r"(a) : "l"(p));
    return a;
}

__device__ __forceinline__ void mma_tf32(float* c, const uint32_t* a,
                                         uint32_t b0, uint32_t b1) {
    asm volatile(
        "mma.sync.aligned.m16n8k8.row.col.f32.tf32.tf32.f32 "
        "{%0,%1,%2,%3}, {%4,%5,%6,%7}, {%8,%9}, {%0,%1,%2,%3};"
        : "+f"(c[0]), "+f"(c[1]), "+f"(c[2]), "+f"(c[3])
        : "r"(a[0]), "r"(a[1]), "r"(a[2]), "r"(a[3]), "r"(b0), "r"(b1));
}

// ---------------- tf32 rounding pass ----------------------------------------
__global__ __launch_bounds__(256) void round_tf32(const float4* __restrict__ in,
                                                  float4* __restrict__ out, int n4) {
    int i = blockIdx.x * 256 + threadIdx.x;
    if (i < n4) {
        float4 v = in[i];
        v.x = tf32r(v.x); v.y = tf32r(v.y); v.z = tf32r(v.z); v.w = tf32r(v.w);
        out[i] = v;
    }
}

// ================ mma.sync tf32 GEMM: C = A @ W^T + bias ====================
// A: [M,K] rm (tf32-rounded), W: [N,K] rm (tf32-rounded). BM=BN=128, BK=32.
// 256 threads = 8 warps, warp grid 4(m) x 2(n), warp tile 32x64.
#define APITCH 36                        // floats; 144B rows, 16B aligned
#define OPER_FLOATS (128 * APITCH)       // 4608
#define STAGE_FLOATS (2 * OPER_FLOATS)   // 9216 (A then W)
#define NSTAGE 3
#define GSMEM_BYTES (NSTAGE * STAGE_FLOATS * 4)   // 110592

__global__ __launch_bounds__(256) void gemm_mma(
    const float* __restrict__ A, const float* __restrict__ W,
    const float* __restrict__ bias, float* __restrict__ C,
    int M, int N, int K)
{
    extern __shared__ float sm[];
    const uint32_t sb = smem_u32(sm);
    const int tid  = threadIdx.x;
    const int wid  = tid >> 5, lane = tid & 31;
    const int g    = lane >> 2, t = lane & 3;
    const int wm   = wid >> 1, wn = wid & 1;
    const int m0   = blockIdx.y * 128;
    const int n0   = blockIdx.x * 128;
    const int NT   = K >> 5;

    const float* Abase = A + (size_t)m0 * K;
    const float* Wbase = W + (size_t)n0 * K;

    auto load_stage = [&](int s) {
        uint32_t soff = sb + (s % NSTAGE) * (STAGE_FLOATS * 4);
        const float* Ag = Abase + s * 32;
        const float* Wg = Wbase + s * 32;
#pragma unroll
        for (int i = 0; i < 4; ++i) {
            int c = tid + i * 256;              // 0..1023
            int row = c >> 3, kc = c & 7;
            uint32_t d = soff + row * 144 + kc * 16;
            CP_ASYNC16(d,                      Ag + (size_t)row * K + kc * 4);
            CP_ASYNC16(d + OPER_FLOATS * 4,    Wg + (size_t)row * K + kc * 4);
        }
        CP_COMMIT();
    };

    float acc[2][8][4];
#pragma unroll
    for (int mt = 0; mt < 2; ++mt)
#pragma unroll
        for (int nt = 0; nt < 8; ++nt)
#pragma unroll
            for (int q = 0; q < 4; ++q) acc[mt][nt][q] = 0.f;

    load_stage(0); load_stage(1); load_stage(2);

    for (int tt = 0; tt < NT; ++tt) {
        CP_WAIT(2);
        __syncthreads();
        const float* As = sm + (tt % NSTAGE) * STAGE_FLOATS;
        const float* Ws = As + OPER_FLOATS;

#pragma unroll
        for (int k8 = 0; k8 < 4; ++k8) {
            const int kk = k8 * 8;
            uint32_t a[2][4];
#pragma unroll
            for (int mt = 0; mt < 2; ++mt) {
                int r0 = wm * 32 + mt * 16 + g;
                a[mt][0] = __float_as_uint(As[r0 * APITCH + kk + t]);
                a[mt][1] = __float_as_uint(As[(r0 + 8) * APITCH + kk + t]);
                a[mt][2] = __float_as_uint(As[r0 * APITCH + kk + t + 4]);
                a[mt][3] = __float_as_uint(As[(r0 + 8) * APITCH + kk + t + 4]);
            }
#pragma unroll
            for (int nt = 0; nt < 8; ++nt) {
                int n = wn * 64 + nt * 8 + g;
                uint32_t b0 = __float_as_uint(Ws[n * APITCH + kk + t]);
                uint32_t b1 = __float_as_uint(Ws[n * APITCH + kk + t + 4]);
                mma_tf32(acc[0][nt], a[0], b0, b1);
                mma_tf32(acc[1][nt], a[1], b0, b1);
            }
        }
        __syncthreads();
        if (tt + 3 < NT) load_stage(tt + 3);
    }

    // epilogue: C = acc + bias
#pragma unroll
    for (int nt = 0; nt < 8; ++nt) {
        int col = n0 + wn * 64 + nt * 8 + t * 2;
        float2 bj = *(const float2*)&bias[col];
#pragma unroll
        for (int mt = 0; mt < 2; ++mt) {
            int r0 = m0 + wm * 32 + mt * 16 + g;
            float2 v0 = make_float2(acc[mt][nt][0] + bj.x, acc[mt][nt][1] + bj.y);
            float2 v1 = make_float2(acc[mt][nt][2] + bj.x, acc[mt][nt][3] + bj.y);
            *(float2*)&C[(size_t)r0 * N + col]       = v0;
            *(float2*)&C[(size_t)(r0 + 8) * N + col] = v1;
        }
    }
}

// ---------------- Flash-style attention (fp32; epilogue rounds to tf32) -----
#define BQ 64
#define BKT 64
#define QPITCH 132
#define KPITCH 68
#define SPITCH 65

#define ATTN_SMEM_FLOATS (BQ*QPITCH + DHD*KPITCH + BKT*QPITCH + BQ*SPITCH + 3*BQ + BKT)
#define ATTN_SMEM_BYTES  (ATTN_SMEM_FLOATS * 4)

__global__ __launch_bounds__(256) void attn_kernel(
    const float* __restrict__ Qm, const float* __restrict__ Km,
    const float* __restrict__ Vm, const int* __restrict__ mask,
    float* __restrict__ ctx)
{
    extern __shared__ float sm[];
    float* Qs   = sm;
    float* Kts  = Qs  + BQ  * QPITCH;
    float* Vs   = Kts + DHD * KPITCH;
    float* Sb   = Vs  + BKT * QPITCH;
    float* rowm = Sb  + BQ  * SPITCH;
    float* rowl = rowm + BQ;
    float* rowscale = rowl + BQ;
    int*   mk   = (int*)(rowscale + BQ);

    const int b  = blockIdx.z;
    const int h  = blockIdx.y;
    const int q0 = blockIdx.x * BQ;
    const int tid = threadIdx.x;
    const int ti = tid >> 4;
    const int tj = tid & 15;
    const float scale = 0.08838834764831845f;

    const float* Qbase = Qm + (size_t)(b * QLEN + q0) * DIM + h * DHD;
#pragma unroll
    for (int it = 0; it < 8; ++it) {
        int idx = tid + it * 256;
        int r = idx >> 5, c4 = idx & 31;
        float4 v = *(const float4*)(Qbase + (size_t)r * DIM + c4 * 4);
        *(float4*)&Qs[r * QPITCH + c4 * 4] = v;
    }
    if (tid < BQ) { rowm[tid] = -1e30f; rowl[tid] = 0.f; }

    float acc[4][8];
#pragma unroll
    for (int i = 0; i < 4; ++i)
#pragma unroll
        for (int c = 0; c < 8; ++c) acc[i][c] = 0.f;

    __syncthreads();

    for (int k0 = 0; k0 < QLEN; k0 += BKT) {
        const float* Kbase = Km + (size_t)(b * QLEN + k0) * DIM + h * DHD;
        const float* Vbase = Vm + (size_t)(b * QLEN + k0) * DIM + h * DHD;
#pragma unroll
        for (int it = 0; it < 8; ++it) {
            int idx = tid + it * 256;
            int r = idx >> 5, c4 = idx & 31;
            float4 kv = *(const float4*)(Kbase + (size_t)r * DIM + c4 * 4);
            Kts[(c4 * 4 + 0) * KPITCH + r] = kv.x;
            Kts[(c4 * 4 + 1) * KPITCH + r] = kv.y;
            Kts[(c4 * 4 + 2) * KPITCH + r] = kv.z;
            Kts[(c4 * 4 + 3) * KPITCH + r] = kv.w;
            float4 vv = *(const float4*)(Vbase + (size_t)r * DIM + c4 * 4);
            *(float4*)&Vs[r * QPITCH + c4 * 4] = vv;
        }
        if (tid < BKT) mk[tid] = mask[b * QLEN + k0 + tid];
        __syncthreads();

        float s[4][4];
#pragma unroll
        for (int i = 0; i < 4; ++i)
#pragma unroll
            for (int j = 0; j < 4; ++j) s[i][j] = 0.f;

#pragma unroll 8
        for (int d = 0; d < DHD; ++d) {
            float4 kv = *(const float4*)&Kts[d * KPITCH + tj * 4];
            float qv0 = Qs[(ti * 4 + 0) * QPITCH + d];
            float qv1 = Qs[(ti * 4 + 1) * QPITCH + d];
            float qv2 = Qs[(ti * 4 + 2) * QPITCH + d];
            float qv3 = Qs[(ti * 4 + 3) * QPITCH + d];
            s[0][0] = fmaf(qv0, kv.x, s[0][0]); s[0][1] = fmaf(qv0, kv.y, s[0][1]);
            s[0][2] = fmaf(qv0, kv.z, s[0][2]); s[0][3] = fmaf(qv0, kv.w, s[0][3]);
            s[1][0] = fmaf(qv1, kv.x, s[1][0]); s[1][1] = fmaf(qv1, kv.y, s[1][1]);
            s[1][2] = fmaf(qv1, kv.z, s[1][2]); s[1][3] = fmaf(qv1, kv.w, s[1][3]);
            s[2][0] = fmaf(qv2, kv.x, s[2][0]); s[2][1] = fmaf(qv2, kv.y, s[2][1]);
            s[2][2] = fmaf(qv2, kv.z, s[2][2]); s[2][3] = fmaf(qv2, kv.w, s[2][3]);
            s[3][0] = fmaf(qv3, kv.x, s[3][0]); s[3][1] = fmaf(qv3, kv.y, s[3][1]);
            s[3][2] = fmaf(qv3, kv.z, s[3][2]); s[3][3] = fmaf(qv3, kv.w, s[3][3]);
        }

#pragma unroll
        for (int jj = 0; jj < 4; ++jj) {
            int j = tj * 4 + jj;
            bool live = (mk[j] != 0);
#pragma unroll
            for (int ii = 0; ii < 4; ++ii) {
                float v = live ? s[ii][jj] * scale : -1e30f;
                Sb[(ti * 4 + ii) * SPITCH + j] = v;
            }
        }
        __syncthreads();

        if (tid < BQ) {
            float mold = rowm[tid];
            float mx = mold;
            float* srow = &Sb[tid * SPITCH];
#pragma unroll 8
            for (int j = 0; j < BKT; ++j) mx = fmaxf(mx, srow[j]);
            float corr = __expf(mold - mx);
            float l = rowl[tid] * corr;
#pragma unroll 8
            for (int j = 0; j < BKT; ++j) {
                float p = __expf(srow[j] - mx);
                srow[j] = p;
                l += p;
            }
            rowm[tid] = mx; rowl[tid] = l; rowscale[tid] = corr;
        }
        __syncthreads();

#pragma unroll
        for (int ii = 0; ii < 4; ++ii) {
            float cs = rowscale[ti * 4 + ii];
#pragma unroll
            for (int c = 0; c < 8; ++c) acc[ii][c] *= cs;
        }
#pragma unroll 4
        for (int j = 0; j < BKT; ++j) {
            float4 v0 = *(const float4*)&Vs[j * QPITCH + tj * 8];
            float4 v1 = *(const float4*)&Vs[j * QPITCH + tj * 8 + 4];
#pragma unroll
            for (int ii = 0; ii < 4; ++ii) {
                float p = Sb[(ti * 4 + ii) * SPITCH + j];
                acc[ii][0] = fmaf(p, v0.x, acc[ii][0]);
                acc[ii][1] = fmaf(p, v0.y, acc[ii][1]);
                acc[ii][2] = fmaf(p, v0.z, acc[ii][2]);
                acc[ii][3] = fmaf(p, v0.w, acc[ii][3]);
                acc[ii][4] = fmaf(p, v1.x, acc[ii][4]);
                acc[ii][5] = fmaf(p, v1.y, acc[ii][5]);
                acc[ii][6] = fmaf(p, v1.z, acc[ii][6]);
                acc[ii][7] = fmaf(p, v1.w, acc[ii][7]);
            }
        }
        __syncthreads();
    }

    // epilogue: divide by l, round to tf32 (feeds tf32 MMA output GEMM)
#pragma unroll
    for (int ii = 0; ii < 4; ++ii) {
        int row = ti * 4 + ii;
        float inv = 1.0f / rowl[row];
        float* op = ctx + (size_t)(b * QLEN + q0 + row) * DIM + h * DHD + tj * 8;
#pragma unroll
        for (int c = 0; c < 8; ++c) op[c] = tf32r(acc[ii][c] * inv);
    }
}

// ---------------- launch -----------------------------------------------------
extern "C" void kernel_launch(void* const* d_in, const int* in_sizes, int n_in,
                              void* d_out, int out_size)
{
    const float* x    = (const float*)d_in[0];
    const int*   mask = (const int*)d_in[1];
    const float* wq   = (const float*)d_in[2];
    const float* bq   = (const float*)d_in[3];
    const float* wk   = (const float*)d_in[4];
    const float* bk   = (const float*)d_in[5];
    const float* wv   = (const float*)d_in[6];
    const float* bv   = (const float*)d_in[7];
    const float* wo   = (const float*)d_in[8];
    const float* bo   = (const float*)d_in[9];
    float* out = (float*)d_out;

    float *gq, *gk, *gv, *gctx, *gxr, *gwr;
    cudaGetSymbolAddress((void**)&gq,   g_q);
    cudaGetSymbolAddress((void**)&gk,   g_k);
    cudaGetSymbolAddress((void**)&gv,   g_v);
    cudaGetSymbolAddress((void**)&gctx, g_ctx);
    cudaGetSymbolAddress((void**)&gxr,  g_xr);
    cudaGetSymbolAddress((void**)&gwr,  g_wr);
    float* gwq = gwr;
    float* gwk = gwr + (size_t)DIM * DIM;
    float* gwv = gwr + 2 * (size_t)DIM * DIM;
    float* gwo = gwr + 3 * (size_t)DIM * DIM;

    // tf32 rounding passes
    const int nx4 = MTOK * DIM / 4;
    const int nw4 = DIM * DIM / 4;
    round_tf32<<<(nx4 + 255) / 256, 256>>>((const float4*)x,  (float4*)gxr, nx4);
    round_tf32<<<(nw4 + 255) / 256, 256>>>((const float4*)wq, (float4*)gwq, nw4);
    round_tf32<<<(nw4 + 255) / 256, 256>>>((const float4*)wk, (float4*)gwk, nw4);
    round_tf32<<<(nw4 + 255) / 256, 256>>>((const float4*)wv, (float4*)gwv, nw4);
    round_tf32<<<(nw4 + 255) / 256, 256>>>((const float4*)wo, (float4*)gwo, nw4);

    cudaFuncSetAttribute(gemm_mma, cudaFuncAttributeMaxDynamicSharedMemorySize,
                         GSMEM_BYTES);
    dim3 gemm_grid(DIM / 128, MTOK / 128);   // (16, 32)
    gemm_mma<<<gemm_grid, 256, GSMEM_BYTES>>>(gxr, gwq, bq, gq, MTOK, DIM, DIM);
    gemm_mma<<<gemm_grid, 256, GSMEM_BYTES>>>(gxr, gwk, bk, gk, MTOK, DIM, DIM);
    gemm_mma<<<gemm_grid, 256, GSMEM_BYTES>>>(gxr, gwv, bv, gv, MTOK, DIM, DIM);

    cudaFuncSetAttribute(attn_kernel, cudaFuncAttributeMaxDynamicSharedMemorySize,
                         ATTN_SMEM_BYTES);
    attn_kernel<<<dim3(QLEN / BQ, NH, BSZ), 256, ATTN_SMEM_BYTES>>>(
        gq, gk, gv, mask, gctx);

    gemm_mma<<<gemm_grid, 256, GSMEM_BYTES>>>(gctx, gwo, bo, out, MTOK, DIM, DIM);
}

// round 5
// speedup vs baseline: 2.7267x; 1.7196x over previous
#include <cuda_runtime.h>
#include <cuda_bf16.h>
#include <cstdint>

#define BSZ   2
#define QLEN  2048
#define DIM   2048
#define NH    16
#define DHD   128
#define MTOK  (BSZ * QLEN)   // 4096

// ---------------- scratch (static device memory; no allocation) -------------
__device__ float g_q[(size_t)MTOK * DIM];
__device__ float g_k[(size_t)MTOK * DIM];
__device__ float g_v[(size_t)MTOK * DIM];
__device__ float g_ctx[(size_t)MTOK * DIM];
__device__ float g_xr[(size_t)MTOK * DIM];          // tf32-rounded input
__device__ float g_wr[4][(size_t)DIM * DIM];        // tf32-rounded weights

// ======================= helpers =============================================
__device__ __forceinline__ float tf32r(float x) {
    uint32_t r;
    asm("cvt.rna.tf32.f32 %0, %1;" : "=r"(r) : "f"(x));
    return __uint_as_float(r);
}

#define CP_ASYNC16(dst, src) \
    asm volatile("cp.async.cg.shared.global [%0], [%1], 16;" :: "r"(dst), "l"(src))
#define CP_COMMIT() asm volatile("cp.async.commit_group;" ::: "memory")
#define CP_WAIT(n)  asm volatile("cp.async.wait_group %0;" :: "n"(n) : "memory")

__device__ __forceinline__ uint32_t smem_u32(const void* p) {
    uint32_t a;
    asm("{ .reg .u64 t; cvta.to.shared.u64 t, %1; cvt.u32.u64 %0, t; }"
        : "=r"(a) : "l"(p));
    return a;
}

__device__ __forceinline__ void mma_tf32(float* c, const uint32_t* a,
                                         uint32_t b0, uint32_t b1) {
    asm volatile(
        "mma.sync.aligned.m16n8k8.row.col.f32.tf32.tf32.f32 "
        "{%0,%1,%2,%3}, {%4,%5,%6,%7}, {%8,%9}, {%0,%1,%2,%3};"
        : "+f"(c[0]), "+f"(c[1]), "+f"(c[2]), "+f"(c[3])
        : "r"(a[0]), "r"(a[1]), "r"(a[2]), "r"(a[3]), "r"(b0), "r"(b1));
}

// ---------------- tf32 rounding pass ----------------------------------------
__global__ __launch_bounds__(256) void round_tf32(const float4* __restrict__ in,
                                                  float4* __restrict__ out, int n4) {
    int i = blockIdx.x * 256 + threadIdx.x;
    if (i < n4) {
        float4 v = in[i];
        v.x = tf32r(v.x); v.y = tf32r(v.y); v.z = tf32r(v.z); v.w = tf32r(v.w);
        out[i] = v;
    }
}

// ================ mma.sync tf32 GEMM: C = A @ W^T + bias ====================
#define APITCH 36
#define OPER_FLOATS (128 * APITCH)
#define STAGE_FLOATS (2 * OPER_FLOATS)
#define NSTAGE 3
#define GSMEM_BYTES (NSTAGE * STAGE_FLOATS * 4)   // 110592

template <bool ROUND_OUT>
__device__ __forceinline__ void gemm_body(
    const float* __restrict__ A, const float* __restrict__ W,
    const float* __restrict__ bias, float* __restrict__ C,
    int M, int N, int K)
{
    extern __shared__ float sm[];
    const uint32_t sb = smem_u32(sm);
    const int tid  = threadIdx.x;
    const int wid  = tid >> 5, lane = tid & 31;
    const int g    = lane >> 2, t = lane & 3;
    const int wm   = wid >> 1, wn = wid & 1;
    const int m0   = blockIdx.y * 128;
    const int n0   = blockIdx.x * 128;
    const int NT   = K >> 5;

    const float* Abase = A + (size_t)m0 * K;
    const float* Wbase = W + (size_t)n0 * K;

    auto load_stage = [&](int s) {
        uint32_t soff = sb + (s % NSTAGE) * (STAGE_FLOATS * 4);
        const float* Ag = Abase + s * 32;
        const float* Wg = Wbase + s * 32;
#pragma unroll
        for (int i = 0; i < 4; ++i) {
            int c = tid + i * 256;
            int row = c >> 3, kc = c & 7;
            uint32_t d = soff + row * 144 + kc * 16;
            CP_ASYNC16(d,                   Ag + (size_t)row * K + kc * 4);
            CP_ASYNC16(d + OPER_FLOATS * 4, Wg + (size_t)row * K + kc * 4);
        }
        CP_COMMIT();
    };

    float acc[2][8][4];
#pragma unroll
    for (int mt = 0; mt < 2; ++mt)
#pragma unroll
        for (int nt = 0; nt < 8; ++nt)
#pragma unroll
            for (int q = 0; q < 4; ++q) acc[mt][nt][q] = 0.f;

    load_stage(0); load_stage(1); load_stage(2);

    for (int tt = 0; tt < NT; ++tt) {
        CP_WAIT(2);
        __syncthreads();
        const float* As = sm + (tt % NSTAGE) * STAGE_FLOATS;
        const float* Ws = As + OPER_FLOATS;

#pragma unroll
        for (int k8 = 0; k8 < 4; ++k8) {
            const int kk = k8 * 8;
            uint32_t a[2][4];
#pragma unroll
            for (int mt = 0; mt < 2; ++mt) {
                int r0 = wm * 32 + mt * 16 + g;
                a[mt][0] = __float_as_uint(As[r0 * APITCH + kk + t]);
                a[mt][1] = __float_as_uint(As[(r0 + 8) * APITCH + kk + t]);
                a[mt][2] = __float_as_uint(As[r0 * APITCH + kk + t + 4]);
                a[mt][3] = __float_as_uint(As[(r0 + 8) * APITCH + kk + t + 4]);
            }
#pragma unroll
            for (int nt = 0; nt < 8; ++nt) {
                int n = wn * 64 + nt * 8 + g;
                uint32_t b0 = __float_as_uint(Ws[n * APITCH + kk + t]);
                uint32_t b1 = __float_as_uint(Ws[n * APITCH + kk + t + 4]);
                mma_tf32(acc[0][nt], a[0], b0, b1);
                mma_tf32(acc[1][nt], a[1], b0, b1);
            }
        }
        __syncthreads();
        if (tt + 3 < NT) load_stage(tt + 3);
    }

#pragma unroll
    for (int nt = 0; nt < 8; ++nt) {
        int col = n0 + wn * 64 + nt * 8 + t * 2;
        float2 bj = *(const float2*)&bias[col];
#pragma unroll
        for (int mt = 0; mt < 2; ++mt) {
            int r0 = m0 + wm * 32 + mt * 16 + g;
            float o0 = acc[mt][nt][0] + bj.x, o1 = acc[mt][nt][1] + bj.y;
            float o2 = acc[mt][nt][2] + bj.x, o3 = acc[mt][nt][3] + bj.y;
            if (ROUND_OUT) { o0 = tf32r(o0); o1 = tf32r(o1); o2 = tf32r(o2); o3 = tf32r(o3); }
            *(float2*)&C[(size_t)r0 * N + col]       = make_float2(o0, o1);
            *(float2*)&C[(size_t)(r0 + 8) * N + col] = make_float2(o2, o3);
        }
    }
}

// merged QKV (z picks the weight/bias/output triple); outputs tf32-rounded.
__global__ __launch_bounds__(256) void gemm_qkv(
    const float* __restrict__ A,
    const float* __restrict__ W0, const float* __restrict__ W1, const float* __restrict__ W2,
    const float* __restrict__ b0, const float* __restrict__ b1, const float* __restrict__ b2,
    float* __restrict__ C0, float* __restrict__ C1, float* __restrict__ C2)
{
    const int z = blockIdx.z;
    const float* W = (z == 0) ? W0 : (z == 1) ? W1 : W2;
    const float* B = (z == 0) ? b0 : (z == 1) ? b1 : b2;
    float*       C = (z == 0) ? C0 : (z == 1) ? C1 : C2;
    gemm_body<true>(A, W, B, C, MTOK, DIM, DIM);
}

__global__ __launch_bounds__(256) void gemm_out(
    const float* __restrict__ A, const float* __restrict__ W,
    const float* __restrict__ bias, float* __restrict__ C)
{
    gemm_body<false>(A, W, bias, C, MTOK, DIM, DIM);
}

// ================ tf32 mma flash attention ==================================
// BQ=128 rows/CTA, 8 warps x 16 rows; BK=64; K/V double-buffered cp.async.
#define ABQ 128
#define ABK 64
#define KP2 132      // K tile pitch (floats): (4g+t) bank bijection
#define VP2 136      // V tile pitch: (8t+g) bank bijection
#define PP2 68       // P tile pitch: (4g+t) bank bijection

#define SM_K0 0
#define SM_K1 (SM_K0 + 64 * KP2)
#define SM_V0 (SM_K1 + 64 * KP2)
#define SM_V1 (SM_V0 + 64 * VP2)
#define SM_P  (SM_V1 + 64 * VP2)
#define SM_MK (SM_P + 128 * PP2)
#define ATT_FLOATS (SM_MK + 128)
#define ATT_BYTES (ATT_FLOATS * 4)     // 172544

__global__ __launch_bounds__(256, 1) void attn_mma(
    const float* __restrict__ Qm, const float* __restrict__ Km,
    const float* __restrict__ Vm, const int* __restrict__ mask,
    float* __restrict__ ctx)
{
    extern __shared__ float sm[];
    const uint32_t sb = smem_u32(sm);
    const int tid = threadIdx.x, wid = tid >> 5, lane = tid & 31;
    const int g = lane >> 2, t = lane & 3;
    const int b = blockIdx.z, h = blockIdx.y, q0 = blockIdx.x * ABQ;
    const int wrow = wid * 16;
    const float scale = 0.08838834764831845f;   // 1/sqrt(128)
    const int NBLK = QLEN / ABK;                // 32

    auto load_kv = [&](int blk) {
        int bi = blk & 1;
        const float* Kg = Km + ((size_t)(b * QLEN) + blk * ABK) * DIM + h * DHD;
        const float* Vg = Vm + ((size_t)(b * QLEN) + blk * ABK) * DIM + h * DHD;
        uint32_t kbase = sb + (bi ? SM_K1 : SM_K0) * 4;
        uint32_t vbase = sb + (bi ? SM_V1 : SM_V0) * 4;
#pragma unroll
        for (int i = 0; i < 8; ++i) {
            int c = tid + i * 256;              // 0..2047
            int r = c >> 5, c4 = c & 31;        // 64 rows x 32 float4
            CP_ASYNC16(kbase + (r * KP2 + c4 * 4) * 4, Kg + (size_t)r * DIM + c4 * 4);
            CP_ASYNC16(vbase + (r * VP2 + c4 * 4) * 4, Vg + (size_t)r * DIM + c4 * 4);
        }
        if (tid < 16)
            CP_ASYNC16(sb + (SM_MK + bi * 64) * 4 + tid * 16,
                       mask + b * QLEN + blk * ABK + tid * 4);
        CP_COMMIT();
    };

    // Q fragments (already tf32 bits from the QKV GEMM epilogue)
    uint32_t qa[16][4];
    {
        const float* Qg = Qm + ((size_t)(b * QLEN) + q0 + wrow) * DIM + h * DHD;
#pragma unroll
        for (int kk = 0; kk < 16; ++kk) {
            qa[kk][0] = __float_as_uint(Qg[(size_t)g * DIM + kk * 8 + t]);
            qa[kk][1] = __float_as_uint(Qg[(size_t)(g + 8) * DIM + kk * 8 + t]);
            qa[kk][2] = __float_as_uint(Qg[(size_t)g * DIM + kk * 8 + t + 4]);
            qa[kk][3] = __float_as_uint(Qg[(size_t)(g + 8) * DIM + kk * 8 + t + 4]);
        }
    }

    float oacc[16][4];
#pragma unroll
    for (int nf = 0; nf < 16; ++nf)
#pragma unroll
        for (int q = 0; q < 4; ++q) oacc[nf][q] = 0.f;
    float mrow0 = -1e30f, mrow1 = -1e30f, lrow0 = 0.f, lrow1 = 0.f;

    load_kv(0); load_kv(1);

    for (int blk = 0; blk < NBLK; ++blk) {
        CP_WAIT(1);
        __syncthreads();
        const int bi = blk & 1;
        const float* Ks = sm + (bi ? SM_K1 : SM_K0);
        const float* Vs = sm + (bi ? SM_V1 : SM_V0);
        const int*   mk = (const int*)(sm + SM_MK) + bi * 64;

        // ---- S = Q K^T (16 x 64 per warp) ----
        float sacc[8][4];
#pragma unroll
        for (int nf = 0; nf < 8; ++nf)
#pragma unroll
            for (int q = 0; q < 4; ++q) sacc[nf][q] = 0.f;

#pragma unroll
        for (int kk = 0; kk < 16; ++kk) {
#pragma unroll
            for (int nf = 0; nf < 8; ++nf) {
                uint32_t b0 = __float_as_uint(Ks[(nf * 8 + g) * KP2 + kk * 8 + t]);
                uint32_t b1 = __float_as_uint(Ks[(nf * 8 + g) * KP2 + kk * 8 + t + 4]);
                mma_tf32(sacc[nf], qa[kk], b0, b1);
            }
        }

        // ---- masked scale + online softmax ----
        float pm0 = -1e30f, pm1 = -1e30f;
#pragma unroll
        for (int nf = 0; nf < 8; ++nf) {
            int j0 = nf * 8 + 2 * t, j1 = j0 + 1;
            bool a0 = mk[j0] != 0, a1 = mk[j1] != 0;
            sacc[nf][0] = a0 ? sacc[nf][0] * scale : -1e30f;
            sacc[nf][1] = a1 ? sacc[nf][1] * scale : -1e30f;
            sacc[nf][2] = a0 ? sacc[nf][2] * scale : -1e30f;
            sacc[nf][3] = a1 ? sacc[nf][3] * scale : -1e30f;
            pm0 = fmaxf(pm0, fmaxf(sacc[nf][0], sacc[nf][1]));
            pm1 = fmaxf(pm1, fmaxf(sacc[nf][2], sacc[nf][3]));
        }
        pm0 = fmaxf(pm0, __shfl_xor_sync(0xFFFFFFFFu, pm0, 1));
        pm0 = fmaxf(pm0, __shfl_xor_sync(0xFFFFFFFFu, pm0, 2));
        pm1 = fmaxf(pm1, __shfl_xor_sync(0xFFFFFFFFu, pm1, 1));
        pm1 = fmaxf(pm1, __shfl_xor_sync(0xFFFFFFFFu, pm1, 2));

        float mnew0 = fmaxf(mrow0, pm0), mnew1 = fmaxf(mrow1, pm1);
        float corr0 = __expf(mrow0 - mnew0), corr1 = __expf(mrow1 - mnew1);
#pragma unroll
        for (int nf = 0; nf < 16; ++nf) {
            oacc[nf][0] *= corr0; oacc[nf][1] *= corr0;
            oacc[nf][2] *= corr1; oacc[nf][3] *= corr1;
        }

        float ps0 = 0.f, ps1 = 0.f;
        float* Pw = sm + SM_P + wrow * PP2;
#pragma unroll
        for (int nf = 0; nf < 8; ++nf) {
            float p0 = __expf(sacc[nf][0] - mnew0);
            float p1 = __expf(sacc[nf][1] - mnew0);
            float p2 = __expf(sacc[nf][2] - mnew1);
            float p3 = __expf(sacc[nf][3] - mnew1);
            ps0 += p0 + p1; ps1 += p2 + p3;
            int j = nf * 8 + 2 * t;
            *(float2*)&Pw[g * PP2 + j]       = make_float2(tf32r(p0), tf32r(p1));
            *(float2*)&Pw[(g + 8) * PP2 + j] = make_float2(tf32r(p2), tf32r(p3));
        }
        ps0 += __shfl_xor_sync(0xFFFFFFFFu, ps0, 1);
        ps0 += __shfl_xor_sync(0xFFFFFFFFu, ps0, 2);
        ps1 += __shfl_xor_sync(0xFFFFFFFFu, ps1, 1);
        ps1 += __shfl_xor_sync(0xFFFFFFFFu, ps1, 2);
        lrow0 = lrow0 * corr0 + ps0;
        lrow1 = lrow1 * corr1 + ps1;
        mrow0 = mnew0; mrow1 = mnew1;
        __syncwarp();

        // ---- O += P V (16 x 128 per warp) ----
#pragma unroll
        for (int kk = 0; kk < 8; ++kk) {
            uint32_t a[4];
            a[0] = __float_as_uint(Pw[g * PP2 + kk * 8 + t]);
            a[1] = __float_as_uint(Pw[(g + 8) * PP2 + kk * 8 + t]);
            a[2] = __float_as_uint(Pw[g * PP2 + kk * 8 + t + 4]);
            a[3] = __float_as_uint(Pw[(g + 8) * PP2 + kk * 8 + t + 4]);
#pragma unroll
            for (int nf = 0; nf < 16; ++nf) {
                uint32_t b0 = __float_as_uint(Vs[(kk * 8 + t) * VP2 + nf * 8 + g]);
                uint32_t b1 = __float_as_uint(Vs[(kk * 8 + t + 4) * VP2 + nf * 8 + g]);
                mma_tf32(oacc[nf], a, b0, b1);
            }
        }
        __syncthreads();
        if (blk + 2 < NBLK) load_kv(blk + 2);
        else CP_COMMIT();
    }

    // ---- epilogue: O / l, tf32-round for the output GEMM ----
    float inv0 = 1.f / lrow0, inv1 = 1.f / lrow1;
    float* Ob = ctx + ((size_t)(b * QLEN) + q0 + wrow) * DIM + h * DHD;
#pragma unroll
    for (int nf = 0; nf < 16; ++nf) {
        int col = nf * 8 + 2 * t;
        *(float2*)&Ob[(size_t)g * DIM + col] =
            make_float2(tf32r(oacc[nf][0] * inv0), tf32r(oacc[nf][1] * inv0));
        *(float2*)&Ob[(size_t)(g + 8) * DIM + col] =
            make_float2(tf32r(oacc[nf][2] * inv1), tf32r(oacc[nf][3] * inv1));
    }
}

// ---------------- launch -----------------------------------------------------
extern "C" void kernel_launch(void* const* d_in, const int* in_sizes, int n_in,
                              void* d_out, int out_size)
{
    const float* x    = (const float*)d_in[0];
    const int*   mask = (const int*)d_in[1];
    const float* wq   = (const float*)d_in[2];
    const float* bq   = (const float*)d_in[3];
    const float* wk   = (const float*)d_in[4];
    const float* bk   = (const float*)d_in[5];
    const float* wv   = (const float*)d_in[6];
    const float* bv   = (const float*)d_in[7];
    const float* wo   = (const float*)d_in[8];
    const float* bo   = (const float*)d_in[9];
    float* out = (float*)d_out;

    float *gq, *gk, *gv, *gctx, *gxr, *gwr;
    cudaGetSymbolAddress((void**)&gq,   g_q);
    cudaGetSymbolAddress((void**)&gk,   g_k);
    cudaGetSymbolAddress((void**)&gv,   g_v);
    cudaGetSymbolAddress((void**)&gctx, g_ctx);
    cudaGetSymbolAddress((void**)&gxr,  g_xr);
    cudaGetSymbolAddress((void**)&gwr,  g_wr);
    float* gwq = gwr;
    float* gwk = gwr + (size_t)DIM * DIM;
    float* gwv = gwr + 2 * (size_t)DIM * DIM;
    float* gwo = gwr + 3 * (size_t)DIM * DIM;

    const int nx4 = MTOK * DIM / 4;
    const int nw4 = DIM * DIM / 4;
    round_tf32<<<(nx4 + 255) / 256, 256>>>((const float4*)x,  (float4*)gxr, nx4);
    round_tf32<<<(nw4 + 255) / 256, 256>>>((const float4*)wq, (float4*)gwq, nw4);
    round_tf32<<<(nw4 + 255) / 256, 256>>>((const float4*)wk, (float4*)gwk, nw4);
    round_tf32<<<(nw4 + 255) / 256, 256>>>((const float4*)wv, (float4*)gwv, nw4);
    round_tf32<<<(nw4 + 255) / 256, 256>>>((const float4*)wo, (float4*)gwo, nw4);

    cudaFuncSetAttribute(gemm_qkv, cudaFuncAttributeMaxDynamicSharedMemorySize, GSMEM_BYTES);
    cudaFuncSetAttribute(gemm_out, cudaFuncAttributeMaxDynamicSharedMemorySize, GSMEM_BYTES);
    cudaFuncSetAttribute(attn_mma, cudaFuncAttributeMaxDynamicSharedMemorySize, ATT_BYTES);

    dim3 qkv_grid(DIM / 128, MTOK / 128, 3);   // (16, 32, 3)
    gemm_qkv<<<qkv_grid, 256, GSMEM_BYTES>>>(gxr, gwq, gwk, gwv, bq, bk, bv, gq, gk, gv);

    attn_mma<<<dim3(QLEN / ABQ, NH, BSZ), 256, ATT_BYTES>>>(gq, gk, gv, mask, gctx);

    dim3 gemm_grid(DIM / 128, MTOK / 128);
    gemm_out<<<gemm_grid, 256, GSMEM_BYTES>>>(gctx, gwo, bo, out);
}

// round 6
// speedup vs baseline: 4.1669x; 1.5282x over previous
#include <cuda_runtime.h>
#include <cuda_bf16.h>
#include <cstdint>

#define BSZ   2
#define QLEN  2048
#define DIM   2048
#define NH    16
#define DHD   128
#define MTOK  (BSZ * QLEN)   // 4096

// ---------------- scratch (static device memory; no allocation) -------------
__device__ float g_q[(size_t)MTOK * DIM];
__device__ float g_k[(size_t)MTOK * DIM];
__device__ float g_v[(size_t)MTOK * DIM];
__device__ float g_ctx[(size_t)MTOK * DIM];
__device__ float g_xr[(size_t)MTOK * DIM];          // tf32-rounded input
__device__ float g_wr[4][(size_t)DIM * DIM];        // tf32-rounded weights

// ======================= helpers =============================================
__device__ __forceinline__ float tf32r(float x) {
    uint32_t r;
    asm("cvt.rna.tf32.f32 %0, %1;" : "=r"(r) : "f"(x));
    return __uint_as_float(r);
}

#define CP_ASYNC16(dst, src) \
    asm volatile("cp.async.cg.shared.global [%0], [%1], 16;" :: "r"(dst), "l"(src))
#define CP_COMMIT() asm volatile("cp.async.commit_group;" ::: "memory")
#define CP_WAIT(n)  asm volatile("cp.async.wait_group %0;" :: "n"(n) : "memory")

__device__ __forceinline__ uint32_t smem_u32(const void* p) {
    uint32_t a;
    asm("{ .reg .u64 t; cvta.to.shared.u64 t, %1; cvt.u32.u64 %0, t; }"
        : "=r"(a) : "l"(p));
    return a;
}

__device__ __forceinline__ void mma_tf32(float* c, const uint32_t* a,
                                         uint32_t b0, uint32_t b1) {
    asm volatile(
        "mma.sync.aligned.m16n8k8.row.col.f32.tf32.tf32.f32 "
        "{%0,%1,%2,%3}, {%4,%5,%6,%7}, {%8,%9}, {%0,%1,%2,%3};"
        : "+f"(c[0]), "+f"(c[1]), "+f"(c[2]), "+f"(c[3])
        : "r"(a[0]), "r"(a[1]), "r"(a[2]), "r"(a[3]), "r"(b0), "r"(b1));
}

// ---------------- tf32 rounding pass ----------------------------------------
__global__ __launch_bounds__(256) void round_tf32(const float4* __restrict__ in,
                                                  float4* __restrict__ out, int n4) {
    int i = blockIdx.x * 256 + threadIdx.x;
    if (i < n4) {
        float4 v = in[i];
        v.x = tf32r(v.x); v.y = tf32r(v.y); v.z = tf32r(v.z); v.w = tf32r(v.w);
        out[i] = v;
    }
}

// ================ mma.sync tf32 GEMM: C = A @ W^T + bias ====================
// CTA tile 128(m) x 256(n), BK=32. 8 warps (2m x 4n), warp tile 64x64.
// 4-stage cp.async ring, ONE __syncthreads per BK-iter.
#define APITCH   36
#define A_FLOATS (128 * APITCH)             // 4608
#define W_FLOATS (256 * APITCH)             // 9216
#define STAGE_FLOATS (A_FLOATS + W_FLOATS)  // 13824
#define NSTAGE   4
#define GSMEM_BYTES (NSTAGE * STAGE_FLOATS * 4)   // 221184

template <bool ROUND_OUT>
__device__ __forceinline__ void gemm_body(
    const float* __restrict__ A, const float* __restrict__ W,
    const float* __restrict__ bias, float* __restrict__ C,
    int M, int N, int K)
{
    extern __shared__ float sm[];
    const uint32_t sb = smem_u32(sm);
    const int tid  = threadIdx.x;
    const int wid  = tid >> 5, lane = tid & 31;
    const int g    = lane >> 2, t = lane & 3;
    const int wm   = wid >> 2;          // 0..1
    const int wn   = wid & 3;           // 0..3
    const int m0   = blockIdx.y * 128;
    const int n0   = blockIdx.x * 256;
    const int NT   = K >> 5;

    const float* Abase = A + (size_t)m0 * K;
    const float* Wbase = W + (size_t)n0 * K;

    auto load_stage = [&](int s) {
        uint32_t soff = sb + (s & (NSTAGE - 1)) * (STAGE_FLOATS * 4);
        const float* Ag = Abase + s * 32;
        const float* Wg = Wbase + s * 32;
#pragma unroll
        for (int i = 0; i < 12; ++i) {
            int c = tid + i * 256;
            if (i < 4) {                       // A: 1024 float4 (128 rows x 8)
                int row = c >> 3, kc = c & 7;
                CP_ASYNC16(soff + row * 144 + kc * 16,
                           Ag + (size_t)row * K + kc * 4);
            } else {                           // W: 2048 float4 (256 rows x 8)
                int c2 = c - 1024;
                int row = c2 >> 3, kc = c2 & 7;
                CP_ASYNC16(soff + A_FLOATS * 4 + row * 144 + kc * 16,
                           Wg + (size_t)row * K + kc * 4);
            }
        }
        CP_COMMIT();
    };

    float acc[4][8][4];
#pragma unroll
    for (int mt = 0; mt < 4; ++mt)
#pragma unroll
        for (int nf = 0; nf < 8; ++nf)
#pragma unroll
            for (int q = 0; q < 4; ++q) acc[mt][nf][q] = 0.f;

    load_stage(0); load_stage(1); load_stage(2);

    for (int tt = 0; tt < NT; ++tt) {
        CP_WAIT(2);
        __syncthreads();
        if (tt + 3 < NT) load_stage(tt + 3);
        else CP_COMMIT();

        const float* As = sm + (tt & (NSTAGE - 1)) * STAGE_FLOATS;
        const float* Ws = As + A_FLOATS;

#pragma unroll
        for (int k8 = 0; k8 < 4; ++k8) {
            const int kk = k8 * 8;
            uint32_t a[4][4];
#pragma unroll
            for (int mt = 0; mt < 4; ++mt) {
                int r0 = wm * 64 + mt * 16 + g;
                a[mt][0] = __float_as_uint(As[r0 * APITCH + kk + t]);
                a[mt][1] = __float_as_uint(As[(r0 + 8) * APITCH + kk + t]);
                a[mt][2] = __float_as_uint(As[r0 * APITCH + kk + t + 4]);
                a[mt][3] = __float_as_uint(As[(r0 + 8) * APITCH + kk + t + 4]);
            }
#pragma unroll
            for (int nf = 0; nf < 8; ++nf) {
                int n = wn * 64 + nf * 8 + g;
                uint32_t b0 = __float_as_uint(Ws[n * APITCH + kk + t]);
                uint32_t b1 = __float_as_uint(Ws[n * APITCH + kk + t + 4]);
                mma_tf32(acc[0][nf], a[0], b0, b1);
                mma_tf32(acc[1][nf], a[1], b0, b1);
                mma_tf32(acc[2][nf], a[2], b0, b1);
                mma_tf32(acc[3][nf], a[3], b0, b1);
            }
        }
    }

#pragma unroll
    for (int nf = 0; nf < 8; ++nf) {
        int col = n0 + wn * 64 + nf * 8 + t * 2;
        float2 bj = *(const float2*)&bias[col];
#pragma unroll
        for (int mt = 0; mt < 4; ++mt) {
            int r0 = m0 + wm * 64 + mt * 16 + g;
            float o0 = acc[mt][nf][0] + bj.x, o1 = acc[mt][nf][1] + bj.y;
            float o2 = acc[mt][nf][2] + bj.x, o3 = acc[mt][nf][3] + bj.y;
            if (ROUND_OUT) { o0 = tf32r(o0); o1 = tf32r(o1); o2 = tf32r(o2); o3 = tf32r(o3); }
            *(float2*)&C[(size_t)r0 * N + col]       = make_float2(o0, o1);
            *(float2*)&C[(size_t)(r0 + 8) * N + col] = make_float2(o2, o3);
        }
    }
}

// merged QKV (z picks the weight/bias/output triple); outputs tf32-rounded.
__global__ __launch_bounds__(256, 1) void gemm_qkv(
    const float* __restrict__ A,
    const float* __restrict__ W0, const float* __restrict__ W1, const float* __restrict__ W2,
    const float* __restrict__ b0, const float* __restrict__ b1, const float* __restrict__ b2,
    float* __restrict__ C0, float* __restrict__ C1, float* __restrict__ C2)
{
    const int z = blockIdx.z;
    const float* W = (z == 0) ? W0 : (z == 1) ? W1 : W2;
    const float* B = (z == 0) ? b0 : (z == 1) ? b1 : b2;
    float*       C = (z == 0) ? C0 : (z == 1) ? C1 : C2;
    gemm_body<true>(A, W, B, C, MTOK, DIM, DIM);
}

__global__ __launch_bounds__(256, 1) void gemm_out(
    const float* __restrict__ A, const float* __restrict__ W,
    const float* __restrict__ bias, float* __restrict__ C)
{
    gemm_body<false>(A, W, bias, C, MTOK, DIM, DIM);
}

// ================ tf32 mma flash attention ==================================
// BQ=128 rows/CTA, 8 warps x 16 rows; BK=64; K/V double-buffered cp.async.
#define ABQ 128
#define ABK 64
#define KP2 132      // K tile pitch (floats): (4g+t) bank bijection
#define VP2 136      // V tile pitch: (8t+g) bank bijection
#define PP2 68       // P tile pitch: (4g+t) bank bijection

#define SM_K0 0
#define SM_K1 (SM_K0 + 64 * KP2)
#define SM_V0 (SM_K1 + 64 * KP2)
#define SM_V1 (SM_V0 + 64 * VP2)
#define SM_P  (SM_V1 + 64 * VP2)
#define SM_MK (SM_P + 128 * PP2)
#define ATT_FLOATS (SM_MK + 128)
#define ATT_BYTES (ATT_FLOATS * 4)     // 172544

__global__ __launch_bounds__(256, 1) void attn_mma(
    const float* __restrict__ Qm, const float* __restrict__ Km,
    const float* __restrict__ Vm, const int* __restrict__ mask,
    float* __restrict__ ctx)
{
    extern __shared__ float sm[];
    const uint32_t sb = smem_u32(sm);
    const int tid = threadIdx.x, wid = tid >> 5, lane = tid & 31;
    const int g = lane >> 2, t = lane & 3;
    const int b = blockIdx.z, h = blockIdx.y, q0 = blockIdx.x * ABQ;
    const int wrow = wid * 16;
    const float scale = 0.08838834764831845f;   // 1/sqrt(128)
    const int NBLK = QLEN / ABK;                // 32

    auto load_kv = [&](int blk) {
        int bi = blk & 1;
        const float* Kg = Km + ((size_t)(b * QLEN) + blk * ABK) * DIM + h * DHD;
        const float* Vg = Vm + ((size_t)(b * QLEN) + blk * ABK) * DIM + h * DHD;
        uint32_t kbase = sb + (bi ? SM_K1 : SM_K0) * 4;
        uint32_t vbase = sb + (bi ? SM_V1 : SM_V0) * 4;
#pragma unroll
        for (int i = 0; i < 8; ++i) {
            int c = tid + i * 256;              // 0..2047
            int r = c >> 5, c4 = c & 31;        // 64 rows x 32 float4
            CP_ASYNC16(kbase + (r * KP2 + c4 * 4) * 4, Kg + (size_t)r * DIM + c4 * 4);
            CP_ASYNC16(vbase + (r * VP2 + c4 * 4) * 4, Vg + (size_t)r * DIM + c4 * 4);
        }
        if (tid < 16)
            CP_ASYNC16(sb + (SM_MK + bi * 64) * 4 + tid * 16,
                       mask + b * QLEN + blk * ABK + tid * 4);
        CP_COMMIT();
    };

    // Q fragments (already tf32 bits from the QKV GEMM epilogue)
    uint32_t qa[16][4];
    {
        const float* Qg = Qm + ((size_t)(b * QLEN) + q0 + wrow) * DIM + h * DHD;
#pragma unroll
        for (int kk = 0; kk < 16; ++kk) {
            qa[kk][0] = __float_as_uint(Qg[(size_t)g * DIM + kk * 8 + t]);
            qa[kk][1] = __float_as_uint(Qg[(size_t)(g + 8) * DIM + kk * 8 + t]);
            qa[kk][2] = __float_as_uint(Qg[(size_t)g * DIM + kk * 8 + t + 4]);
            qa[kk][3] = __float_as_uint(Qg[(size_t)(g + 8) * DIM + kk * 8 + t + 4]);
        }
    }

    float oacc[16][4];
#pragma unroll
    for (int nf = 0; nf < 16; ++nf)
#pragma unroll
        for (int q = 0; q < 4; ++q) oacc[nf][q] = 0.f;
    float mrow0 = -1e30f, mrow1 = -1e30f, lrow0 = 0.f, lrow1 = 0.f;

    load_kv(0); load_kv(1);

    for (int blk = 0; blk < NBLK; ++blk) {
        CP_WAIT(1);
        __syncthreads();
        const int bi = blk & 1;
        const float* Ks = sm + (bi ? SM_K1 : SM_K0);
        const float* Vs = sm + (bi ? SM_V1 : SM_V0);
        const int*   mk = (const int*)(sm + SM_MK) + bi * 64;

        // ---- S = Q K^T (16 x 64 per warp) ----
        float sacc[8][4];
#pragma unroll
        for (int nf = 0; nf < 8; ++nf)
#pragma unroll
            for (int q = 0; q < 4; ++q) sacc[nf][q] = 0.f;

#pragma unroll
        for (int kk = 0; kk < 16; ++kk) {
#pragma unroll
            for (int nf = 0; nf < 8; ++nf) {
                uint32_t b0 = __float_as_uint(Ks[(nf * 8 + g) * KP2 + kk * 8 + t]);
                uint32_t b1 = __float_as_uint(Ks[(nf * 8 + g) * KP2 + kk * 8 + t + 4]);
                mma_tf32(sacc[nf], qa[kk], b0, b1);
            }
        }

        // ---- masked scale + online softmax ----
        float pm0 = -1e30f, pm1 = -1e30f;
#pragma unroll
        for (int nf = 0; nf < 8; ++nf) {
            int j0 = nf * 8 + 2 * t, j1 = j0 + 1;
            bool a0 = mk[j0] != 0, a1 = mk[j1] != 0;
            sacc[nf][0] = a0 ? sacc[nf][0] * scale : -1e30f;
            sacc[nf][1] = a1 ? sacc[nf][1] * scale : -1e30f;
            sacc[nf][2] = a0 ? sacc[nf][2] * scale : -1e30f;
            sacc[nf][3] = a1 ? sacc[nf][3] * scale : -1e30f;
            pm0 = fmaxf(pm0, fmaxf(sacc[nf][0], sacc[nf][1]));
            pm1 = fmaxf(pm1, fmaxf(sacc[nf][2], sacc[nf][3]));
        }
        pm0 = fmaxf(pm0, __shfl_xor_sync(0xFFFFFFFFu, pm0, 1));
        pm0 = fmaxf(pm0, __shfl_xor_sync(0xFFFFFFFFu, pm0, 2));
        pm1 = fmaxf(pm1, __shfl_xor_sync(0xFFFFFFFFu, pm1, 1));
        pm1 = fmaxf(pm1, __shfl_xor_sync(0xFFFFFFFFu, pm1, 2));

        float mnew0 = fmaxf(mrow0, pm0), mnew1 = fmaxf(mrow1, pm1);
        float corr0 = __expf(mrow0 - mnew0), corr1 = __expf(mrow1 - mnew1);
#pragma unroll
        for (int nf = 0; nf < 16; ++nf) {
            oacc[nf][0] *= corr0; oacc[nf][1] *= corr0;
            oacc[nf][2] *= corr1; oacc[nf][3] *= corr1;
        }

        float ps0 = 0.f, ps1 = 0.f;
        float* Pw = sm + SM_P + wrow * PP2;
#pragma unroll
        for (int nf = 0; nf < 8; ++nf) {
            float p0 = __expf(sacc[nf][0] - mnew0);
            float p1 = __expf(sacc[nf][1] - mnew0);
            float p2 = __expf(sacc[nf][2] - mnew1);
            float p3 = __expf(sacc[nf][3] - mnew1);
            ps0 += p0 + p1; ps1 += p2 + p3;
            int j = nf * 8 + 2 * t;
            *(float2*)&Pw[g * PP2 + j]       = make_float2(tf32r(p0), tf32r(p1));
            *(float2*)&Pw[(g + 8) * PP2 + j] = make_float2(tf32r(p2), tf32r(p3));
        }
        ps0 += __shfl_xor_sync(0xFFFFFFFFu, ps0, 1);
        ps0 += __shfl_xor_sync(0xFFFFFFFFu, ps0, 2);
        ps1 += __shfl_xor_sync(0xFFFFFFFFu, ps1, 1);
        ps1 += __shfl_xor_sync(0xFFFFFFFFu, ps1, 2);
        lrow0 = lrow0 * corr0 + ps0;
        lrow1 = lrow1 * corr1 + ps1;
        mrow0 = mnew0; mrow1 = mnew1;
        __syncwarp();

        // ---- O += P V (16 x 128 per warp) ----
#pragma unroll
        for (int kk = 0; kk < 8; ++kk) {
            uint32_t a[4];
            a[0] = __float_as_uint(Pw[g * PP2 + kk * 8 + t]);
            a[1] = __float_as_uint(Pw[(g + 8) * PP2 + kk * 8 + t]);
            a[2] = __float_as_uint(Pw[g * PP2 + kk * 8 + t + 4]);
            a[3] = __float_as_uint(Pw[(g + 8) * PP2 + kk * 8 + t + 4]);
#pragma unroll
            for (int nf = 0; nf < 16; ++nf) {
                uint32_t b0 = __float_as_uint(Vs[(kk * 8 + t) * VP2 + nf * 8 + g]);
                uint32_t b1 = __float_as_uint(Vs[(kk * 8 + t + 4) * VP2 + nf * 8 + g]);
                mma_tf32(oacc[nf], a, b0, b1);
            }
        }
        __syncthreads();
        if (blk + 2 < NBLK) load_kv(blk + 2);
        else CP_COMMIT();
    }

    // ---- epilogue: O / l, tf32-round for the output GEMM ----
    float inv0 = 1.f / lrow0, inv1 = 1.f / lrow1;
    float* Ob = ctx + ((size_t)(b * QLEN) + q0 + wrow) * DIM + h * DHD;
#pragma unroll
    for (int nf = 0; nf < 16; ++nf) {
        int col = nf * 8 + 2 * t;
        *(float2*)&Ob[(size_t)g * DIM + col] =
            make_float2(tf32r(oacc[nf][0] * inv0), tf32r(oacc[nf][1] * inv0));
        *(float2*)&Ob[(size_t)(g + 8) * DIM + col] =
            make_float2(tf32r(oacc[nf][2] * inv1), tf32r(oacc[nf][3] * inv1));
    }
}

// ---------------- launch -----------------------------------------------------
extern "C" void kernel_launch(void* const* d_in, const int* in_sizes, int n_in,
                              void* d_out, int out_size)
{
    const float* x    = (const float*)d_in[0];
    const int*   mask = (const int*)d_in[1];
    const float* wq   = (const float*)d_in[2];
    const float* bq   = (const float*)d_in[3];
    const float* wk   = (const float*)d_in[4];
    const float* bk   = (const float*)d_in[5];
    const float* wv   = (const float*)d_in[6];
    const float* bv   = (const float*)d_in[7];
    const float* wo   = (const float*)d_in[8];
    const float* bo   = (const float*)d_in[9];
    float* out = (float*)d_out;

    float *gq, *gk, *gv, *gctx, *gxr, *gwr;
    cudaGetSymbolAddress((void**)&gq,   g_q);
    cudaGetSymbolAddress((void**)&gk,   g_k);
    cudaGetSymbolAddress((void**)&gv,   g_v);
    cudaGetSymbolAddress((void**)&gctx, g_ctx);
    cudaGetSymbolAddress((void**)&gxr,  g_xr);
    cudaGetSymbolAddress((void**)&gwr,  g_wr);
    float* gwq = gwr;
    float* gwk = gwr + (size_t)DIM * DIM;
    float* gwv = gwr + 2 * (size_t)DIM * DIM;
    float* gwo = gwr + 3 * (size_t)DIM * DIM;

    const int nx4 = MTOK * DIM / 4;
    const int nw4 = DIM * DIM / 4;
    round_tf32<<<(nx4 + 255) / 256, 256>>>((const float4*)x,  (float4*)gxr, nx4);
    round_tf32<<<(nw4 + 255) / 256, 256>>>((const float4*)wq, (float4*)gwq, nw4);
    round_tf32<<<(nw4 + 255) / 256, 256>>>((const float4*)wk, (float4*)gwk, nw4);
    round_tf32<<<(nw4 + 255) / 256, 256>>>((const float4*)wv, (float4*)gwv, nw4);
    round_tf32<<<(nw4 + 255) / 256, 256>>>((const float4*)wo, (float4*)gwo, nw4);

    cudaFuncSetAttribute(gemm_qkv, cudaFuncAttributeMaxDynamicSharedMemorySize, GSMEM_BYTES);
    cudaFuncSetAttribute(gemm_out, cudaFuncAttributeMaxDynamicSharedMemorySize, GSMEM_BYTES);
    cudaFuncSetAttribute(attn_mma, cudaFuncAttributeMaxDynamicSharedMemorySize, ATT_BYTES);

    dim3 qkv_grid(DIM / 256, MTOK / 128, 3);   // (8, 32, 3)
    gemm_qkv<<<qkv_grid, 256, GSMEM_BYTES>>>(gxr, gwq, gwk, gwv, bq, bk, bv, gq, gk, gv);

    attn_mma<<<dim3(QLEN / ABQ, NH, BSZ), 256, ATT_BYTES>>>(gq, gk, gv, mask, gctx);

    dim3 gemm_grid(DIM / 256, MTOK / 128);     // (8, 32)
    gemm_out<<<gemm_grid, 256, GSMEM_BYTES>>>(gctx, gwo, bo, out);
}